// round 1
// baseline (speedup 1.0000x reference)
#include <cuda_runtime.h>
#include <cstdint>
#include <math.h>

// ---------------- problem constants ----------------
#define B_  16384
#define N_  10
#define T_  (B_*N_)        // 163840 tokens
#define D_  512

typedef unsigned long long u64;

// ---------------- scratch (static device globals; no allocation) ----------------
__device__ float g_rel[T_*20];          // relationship features
__device__ float g_x  [T_*D_];          // x0 (pre-attention activations)
__device__ float g_x1 [T_*D_];          // x1 (post-LN1)
__device__ float g_att[T_*D_];          // attention output / gelu hidden (reused)
__device__ float g_y  [T_*D_];          // pre-LN sums
__device__ float g_qkv[T_*3*D_];        // fused qkv

// ---------------- packed f32x2 helpers ----------------
__device__ __forceinline__ u64 pack2(float a, float b) {
    u64 r; asm("mov.b64 %0, {%1, %2};" : "=l"(r) : "f"(a), "f"(b)); return r;
}
__device__ __forceinline__ void fma2(u64 &d, u64 a, u64 b) {
    asm("fma.rn.f32x2 %0, %1, %2, %0;" : "+l"(d) : "l"(a), "l"(b));
}
__device__ __forceinline__ float2 unpack2(u64 v) {
    float2 r; asm("mov.b64 {%0, %1}, %2;" : "=f"(r.x), "=f"(r.y) : "l"(v)); return r;
}

__device__ __forceinline__ float warp_sum(float v) {
#pragma unroll
    for (int o = 16; o; o >>= 1) v += __shfl_xor_sync(0xffffffffu, v, o);
    return v;
}

__device__ __forceinline__ float gelu_f(float x) {
    return 0.5f * x * (1.0f + erff(x * 0.70710678118654752440f));
}

// ---------------- kernel 1: boxes -> rel features (top-5 nearest neighbors) ----------------
// one warp per batch element
__global__ void rel_kernel(const float* __restrict__ boxes, float* __restrict__ rel) {
    int gw   = (blockIdx.x * blockDim.x + threadIdx.x) >> 5;
    int lane = threadIdx.x & 31;
    if (gw >= B_) return;

    float cx = 0.f, cy = 0.f, bw = 0.f, bh = 0.f;
    if (lane < N_) {
        float4 bx = *(const float4*)(boxes + ((size_t)gw * N_ + lane) * 4);
        cx = (bx.x + bx.z) * 0.5f * (1.0f / 512.0f);
        cy = (bx.y + bx.w) * 0.5f * (1.0f / 512.0f);
        bw = fabsf(bx.z - bx.x) * (1.0f / 512.0f);
        bh = fabsf(bx.w - bx.y) * (1.0f / 512.0f);
    }

    float bd[5] = {INFINITY, INFINITY, INFINITY, INFINITY, INFINITY};
    int   bj[5] = {0, 0, 0, 0, 0};

#pragma unroll
    for (int j = 0; j < N_; j++) {
        float cxj = __shfl_sync(0xffffffffu, cx, j);
        float cyj = __shfl_sync(0xffffffffu, cy, j);
        float dx = cx - cxj, dy = cy - cyj;
        float d  = dx * dx + dy * dy;
        if (lane < N_ && j != lane && d < bd[4]) {
            int p = 4;
            while (p > 0 && d < bd[p-1]) { bd[p] = bd[p-1]; bj[p] = bj[p-1]; p--; }
            bd[p] = d; bj[p] = j;
        }
    }

#pragma unroll
    for (int k = 0; k < 5; k++) {
        int j = bj[k];
        float cxj = __shfl_sync(0xffffffffu, cx, j);
        float cyj = __shfl_sync(0xffffffffu, cy, j);
        float bwj = __shfl_sync(0xffffffffu, bw, j);
        float bhj = __shfl_sync(0xffffffffu, bh, j);
        if (lane < N_) {
            float4 o4 = make_float4(cxj - cx, cyj - cy, bwj - bw, bhj - bh);
            *(float4*)(rel + ((size_t)gw * N_ + lane) * 20 + k * 4) = o4;
        }
    }
}

// ---------------- kernel 2: x = rel @ w_in^T + b_in ----------------
// block handles 32 tokens; w_in (512x20) cached transposed in smem
__global__ void inproj_kernel(const float* __restrict__ rel, const float* __restrict__ w_in,
                              const float* __restrict__ b_in, float* __restrict__ x) {
    __shared__ float ws[20 * 512];
    __shared__ float rs[32 * 20];
    int tid = threadIdx.x;
    int t0  = blockIdx.x * 32;

    for (int i = tid; i < 20 * 512; i += 256) {
        int d = i / 20, j = i % 20;
        ws[j * 512 + d] = w_in[i];
    }
    for (int i = tid; i < 32 * 20; i += 256)
        rs[i] = rel[(size_t)t0 * 20 + i];
    __syncthreads();

    for (int i = tid; i < 32 * 512; i += 256) {
        int tt = i >> 9, d = i & 511;
        float s = b_in[d];
#pragma unroll
        for (int j = 0; j < 20; j++)
            s = fmaf(rs[tt * 20 + j], ws[j * 512 + d], s);
        x[(size_t)(t0 + tt) * 512 + d] = s;
    }
}

// ---------------- tiled SGEMM: C[M,NOUT] = A[M,512] * W[NOUT,512]^T + epilogue ----------------
// EPI: 0 = +bias ; 1 = +bias +residual ; 2 = +bias then exact GELU
template<int EPI, int NOUT>
__global__ __launch_bounds__(256, 2) void sgemm_kernel(
    const float* __restrict__ A, const float* __restrict__ W,
    const float* __restrict__ bias, const float* __restrict__ res,
    float* __restrict__ C)
{
    __shared__ __align__(16) float As[16][132];
    __shared__ __align__(16) float Ws[16][132];

    const int tid  = threadIdx.x;
    const int bm   = blockIdx.y * 128;
    const int bn   = blockIdx.x * 128;
    const int tm   = tid >> 4;         // 0..15
    const int tn   = tid & 15;         // 0..15
    const int lrow = tid >> 2;         // 0..63
    const int lk   = (tid & 3) << 2;   // 0,4,8,12

    const float* Ap = A + (size_t)(bm + lrow) * 512 + lk;
    const float* Wp = W + (size_t)(bn + lrow) * 512 + lk;

    u64 acc[8][4];
#pragma unroll
    for (int i = 0; i < 8; i++)
#pragma unroll
        for (int p = 0; p < 4; p++) acc[i][p] = 0ull;

    for (int kt = 0; kt < 512; kt += 16) {
        float4 a0 = *(const float4*)(Ap + kt);
        float4 a1 = *(const float4*)(Ap + kt + 64 * 512);
        float4 w0 = *(const float4*)(Wp + kt);
        float4 w1 = *(const float4*)(Wp + kt + 64 * 512);
        __syncthreads();
        As[lk+0][lrow]    = a0.x; As[lk+1][lrow]    = a0.y; As[lk+2][lrow]    = a0.z; As[lk+3][lrow]    = a0.w;
        As[lk+0][lrow+64] = a1.x; As[lk+1][lrow+64] = a1.y; As[lk+2][lrow+64] = a1.z; As[lk+3][lrow+64] = a1.w;
        Ws[lk+0][lrow]    = w0.x; Ws[lk+1][lrow]    = w0.y; Ws[lk+2][lrow]    = w0.z; Ws[lk+3][lrow]    = w0.w;
        Ws[lk+0][lrow+64] = w1.x; Ws[lk+1][lrow+64] = w1.y; Ws[lk+2][lrow+64] = w1.z; Ws[lk+3][lrow+64] = w1.w;
        __syncthreads();

#pragma unroll
        for (int kk = 0; kk < 16; kk++) {
            float4 af0 = *(const float4*)&As[kk][tm * 8];
            float4 af1 = *(const float4*)&As[kk][tm * 8 + 4];
            u64 b0 = *(const u64*)&Ws[kk][tn * 8 + 0];
            u64 b1 = *(const u64*)&Ws[kk][tn * 8 + 2];
            u64 b2 = *(const u64*)&Ws[kk][tn * 8 + 4];
            u64 b3 = *(const u64*)&Ws[kk][tn * 8 + 6];
            float av[8] = {af0.x, af0.y, af0.z, af0.w, af1.x, af1.y, af1.z, af1.w};
#pragma unroll
            for (int i = 0; i < 8; i++) {
                u64 ai = pack2(av[i], av[i]);
                fma2(acc[i][0], ai, b0);
                fma2(acc[i][1], ai, b1);
                fma2(acc[i][2], ai, b2);
                fma2(acc[i][3], ai, b3);
            }
        }
    }

    const int row0 = bm + tm * 8;
    const int col0 = bn + tn * 8;
    float bb[8];
#pragma unroll
    for (int j = 0; j < 8; j++) bb[j] = bias[col0 + j];

#pragma unroll
    for (int i = 0; i < 8; i++) {
        float c[8];
#pragma unroll
        for (int p = 0; p < 4; p++) {
            float2 u = unpack2(acc[i][p]);
            c[2*p]   = u.x + bb[2*p];
            c[2*p+1] = u.y + bb[2*p+1];
        }
        int row = row0 + i;
        if (EPI == 1) {
            float4 r0 = *(const float4*)&res[(size_t)row * 512 + col0];
            float4 r1 = *(const float4*)&res[(size_t)row * 512 + col0 + 4];
            c[0]+=r0.x; c[1]+=r0.y; c[2]+=r0.z; c[3]+=r0.w;
            c[4]+=r1.x; c[5]+=r1.y; c[6]+=r1.z; c[7]+=r1.w;
        }
        if (EPI == 2) {
#pragma unroll
            for (int j = 0; j < 8; j++) c[j] = gelu_f(c[j]);
        }
        *(float4*)&C[(size_t)row * NOUT + col0]     = make_float4(c[0], c[1], c[2], c[3]);
        *(float4*)&C[(size_t)row * NOUT + col0 + 4] = make_float4(c[4], c[5], c[6], c[7]);
    }
}

// ---------------- attention kernel: one block per batch ----------------
// qkv rows (10 x 1536) in padded smem (stride 1540 to break bank conflicts)
__global__ void attn_kernel(const float* __restrict__ qkv, float* __restrict__ o) {
    extern __shared__ __align__(16) float s[];   // 10 * 1540 floats
    __shared__ float satt[200];                  // [h][i][j]
    const int b   = blockIdx.x;
    const int tid = threadIdx.x;
    const float* src = qkv + (size_t)b * (N_ * 3 * D_);

    for (int i = tid; i < (N_ * 3 * D_) / 4; i += 256) {
        int e = i * 4;
        int r = e / 1536, c = e % 1536;
        float4 v = *(const float4*)(src + e);
        *(float4*)(s + r * 1540 + c) = v;
    }
    __syncthreads();

    if (tid < 200) {
        int h = tid / 100;
        int i = (tid / 10) % 10;
        int j = tid % 10;
        const float* qp = s + i * 1540 + h * 256;
        const float* kp = s + j * 1540 + 512 + h * 256;
        float acc = 0.f;
#pragma unroll 8
        for (int d = 0; d < 256; d++) acc = fmaf(qp[d], kp[d], acc);
        satt[tid] = acc * 0.0625f;    // 1/sqrt(256)
    }
    __syncthreads();

    if (tid < 20) {
        int base = tid * 10;
        float m = satt[base];
#pragma unroll
        for (int j = 1; j < 10; j++) m = fmaxf(m, satt[base + j]);
        float e[10]; float sum = 0.f;
#pragma unroll
        for (int j = 0; j < 10; j++) { e[j] = expf(satt[base + j] - m); sum += e[j]; }
        float inv = 1.0f / sum;
#pragma unroll
        for (int j = 0; j < 10; j++) satt[base + j] = e[j] * inv;
    }
    __syncthreads();

    float* dst = o + (size_t)b * (N_ * D_);
    for (int idx = tid; idx < N_ * D_; idx += 256) {
        int d  = idx & 255;
        int hi = idx >> 8;         // 0..19
        int i  = hi % 10, h = hi / 10;
        const float* ap = satt + h * 100 + i * 10;
        const float* vp = s + 1024 + h * 256 + d;
        float acc = 0.f;
#pragma unroll
        for (int j = 0; j < 10; j++) acc = fmaf(ap[j], vp[j * 1540], acc);
        dst[i * 512 + h * 256 + d] = acc;
    }
}

// ---------------- layernorm (one warp per 512-wide row) ----------------
__global__ void ln_kernel(const float* __restrict__ y, const float* __restrict__ g,
                          const float* __restrict__ bt, float* __restrict__ out) {
    int row  = blockIdx.x * 8 + (threadIdx.x >> 5);
    int lane = threadIdx.x & 31;
    const float* p = y + (size_t)row * 512;
    float v[16];
#pragma unroll
    for (int q = 0; q < 4; q++) {
        float4 t = *(const float4*)(p + q * 128 + lane * 4);
        v[q*4+0] = t.x; v[q*4+1] = t.y; v[q*4+2] = t.z; v[q*4+3] = t.w;
    }
    float s = 0.f;
#pragma unroll
    for (int k = 0; k < 16; k++) s += v[k];
    s = warp_sum(s);
    float mu = s * (1.0f / 512.0f);
    float qs = 0.f;
#pragma unroll
    for (int k = 0; k < 16; k++) { float d = v[k] - mu; qs += d * d; }
    qs = warp_sum(qs);
    float inv = rsqrtf(qs * (1.0f / 512.0f) + 1e-5f);

    float* op = out + (size_t)row * 512;
#pragma unroll
    for (int q = 0; q < 4; q++) {
        int d0 = q * 128 + lane * 4;
        float4 r;
        r.x = (v[q*4+0] - mu) * inv * g[d0+0] + bt[d0+0];
        r.y = (v[q*4+1] - mu) * inv * g[d0+1] + bt[d0+1];
        r.z = (v[q*4+2] - mu) * inv * g[d0+2] + bt[d0+2];
        r.w = (v[q*4+3] - mu) * inv * g[d0+3] + bt[d0+3];
        *(float4*)(op + d0) = r;
    }
}

// ---------------- fused LN2 + LNf ----------------
__global__ void ln2f_kernel(const float* __restrict__ y,
                            const float* __restrict__ g2, const float* __restrict__ b2,
                            const float* __restrict__ gf, const float* __restrict__ bf,
                            float* __restrict__ out) {
    int row  = blockIdx.x * 8 + (threadIdx.x >> 5);
    int lane = threadIdx.x & 31;
    const float* p = y + (size_t)row * 512;
    float v[16];
#pragma unroll
    for (int q = 0; q < 4; q++) {
        float4 t = *(const float4*)(p + q * 128 + lane * 4);
        v[q*4+0] = t.x; v[q*4+1] = t.y; v[q*4+2] = t.z; v[q*4+3] = t.w;
    }
    // LN2
    float s = 0.f;
#pragma unroll
    for (int k = 0; k < 16; k++) s += v[k];
    s = warp_sum(s);
    float mu = s * (1.0f / 512.0f);
    float qs = 0.f;
#pragma unroll
    for (int k = 0; k < 16; k++) { float d = v[k] - mu; qs += d * d; }
    qs = warp_sum(qs);
    float inv = rsqrtf(qs * (1.0f / 512.0f) + 1e-5f);
#pragma unroll
    for (int k = 0; k < 16; k++) {
        int d = (k >> 2) * 128 + lane * 4 + (k & 3);
        v[k] = (v[k] - mu) * inv * g2[d] + b2[d];
    }
    // LNf
    s = 0.f;
#pragma unroll
    for (int k = 0; k < 16; k++) s += v[k];
    s = warp_sum(s);
    float mu2 = s * (1.0f / 512.0f);
    qs = 0.f;
#pragma unroll
    for (int k = 0; k < 16; k++) { float d = v[k] - mu2; qs += d * d; }
    qs = warp_sum(qs);
    float inv2 = rsqrtf(qs * (1.0f / 512.0f) + 1e-5f);

    float* op = out + (size_t)row * 512;
#pragma unroll
    for (int q = 0; q < 4; q++) {
        int d0 = q * 128 + lane * 4;
        float4 r;
        r.x = (v[q*4+0] - mu2) * inv2 * gf[d0+0] + bf[d0+0];
        r.y = (v[q*4+1] - mu2) * inv2 * gf[d0+1] + bf[d0+1];
        r.z = (v[q*4+2] - mu2) * inv2 * gf[d0+2] + bf[d0+2];
        r.w = (v[q*4+3] - mu2) * inv2 * gf[d0+3] + bf[d0+3];
        *(float4*)(op + d0) = r;
    }
}

// ---------------- launcher ----------------
extern "C" void kernel_launch(void* const* d_in, const int* in_sizes, int n_in,
                              void* d_out, int out_size) {
    const float* boxes = (const float*)d_in[0];
    const float* w_in  = (const float*)d_in[1];
    const float* b_in  = (const float*)d_in[2];
    const float* wqkv  = (const float*)d_in[3];
    const float* bqkv  = (const float*)d_in[4];
    const float* wo    = (const float*)d_in[5];
    const float* bo    = (const float*)d_in[6];
    const float* ln1w  = (const float*)d_in[7];
    const float* ln1b  = (const float*)d_in[8];
    const float* w1    = (const float*)d_in[9];
    const float* b1    = (const float*)d_in[10];
    const float* w2    = (const float*)d_in[11];
    const float* b2    = (const float*)d_in[12];
    const float* ln2w  = (const float*)d_in[13];
    const float* ln2b  = (const float*)d_in[14];
    const float* lnfw  = (const float*)d_in[15];
    const float* lnfb  = (const float*)d_in[16];
    float* out = (float*)d_out;

    float *rel, *x, *x1, *att, *yb, *qkv;
    cudaGetSymbolAddress((void**)&rel, g_rel);
    cudaGetSymbolAddress((void**)&x,   g_x);
    cudaGetSymbolAddress((void**)&x1,  g_x1);
    cudaGetSymbolAddress((void**)&att, g_att);
    cudaGetSymbolAddress((void**)&yb,  g_y);
    cudaGetSymbolAddress((void**)&qkv, g_qkv);

    // 1) relationships
    rel_kernel<<<B_/4, 128>>>(boxes, rel);
    // 2) input projection
    inproj_kernel<<<T_/32, 256>>>(rel, w_in, b_in, x);
    // 3) qkv = x @ wqkv^T + bqkv
    sgemm_kernel<0, 1536><<<dim3(12, T_/128), 256>>>(x, wqkv, bqkv, nullptr, qkv);
    // 4) attention
    int attn_smem = 10 * 1540 * (int)sizeof(float);
    cudaFuncSetAttribute(attn_kernel, cudaFuncAttributeMaxDynamicSharedMemorySize, attn_smem);
    attn_kernel<<<B_, 256, attn_smem>>>(qkv, att);
    // 5) y1 = x + att @ wo^T + bo
    sgemm_kernel<1, 512><<<dim3(4, T_/128), 256>>>(att, wo, bo, x, yb);
    // 6) x1 = LN1(y1)
    ln_kernel<<<T_/8, 256>>>(yb, ln1w, ln1b, x1);
    // 7) h = gelu(x1 @ w1^T + b1)
    sgemm_kernel<2, 512><<<dim3(4, T_/128), 256>>>(x1, w1, b1, nullptr, att);
    // 8) y2 = x1 + h @ w2^T + b2
    sgemm_kernel<1, 512><<<dim3(4, T_/128), 256>>>(att, w2, b2, x1, yb);
    // 9) out = LNf(LN2(y2))
    ln2f_kernel<<<T_/8, 256>>>(yb, ln2w, ln2b, lnfw, lnfb, out);
}

// round 3
// speedup vs baseline: 1.9479x; 1.9479x over previous
#include <cuda_runtime.h>
#include <cuda_bf16.h>
#include <cstdint>
#include <math.h>

// ---------------- problem constants ----------------
#define B_  16384
#define N_  10
#define T_  (B_*N_)        // 163840 tokens
#define D_  512

typedef unsigned long long u64;
typedef __nv_bfloat16 bf16;

// ---------------- scratch (static device globals; no allocation) ----------------
__device__ __align__(128) float g_rel[T_*20];
__device__ __align__(128) float g_x  [T_*D_];
__device__ __align__(128) float g_x1 [T_*D_];
__device__ __align__(128) float g_y  [T_*D_];
__device__ __align__(128) float g_qkv[T_*3*D_];

__device__ __align__(128) bf16 g_xh [T_*D_];
__device__ __align__(128) bf16 g_xl [T_*D_];
__device__ __align__(128) bf16 g_ath[T_*D_];
__device__ __align__(128) bf16 g_atl[T_*D_];
__device__ __align__(128) bf16 g_x1h[T_*D_];
__device__ __align__(128) bf16 g_x1l[T_*D_];
__device__ __align__(128) bf16 g_hh [T_*D_];
__device__ __align__(128) bf16 g_hl [T_*D_];

__device__ __align__(128) bf16 g_wqh[3*D_*D_];
__device__ __align__(128) bf16 g_wql[3*D_*D_];
__device__ __align__(128) bf16 g_woh[D_*D_];
__device__ __align__(128) bf16 g_wol[D_*D_];
__device__ __align__(128) bf16 g_w1h[D_*D_];
__device__ __align__(128) bf16 g_w1l[D_*D_];
__device__ __align__(128) bf16 g_w2h[D_*D_];
__device__ __align__(128) bf16 g_w2l[D_*D_];

// ---------------- small helpers ----------------
__device__ __forceinline__ float warp_sum(float v) {
#pragma unroll
    for (int o = 16; o; o >>= 1) v += __shfl_xor_sync(0xffffffffu, v, o);
    return v;
}
__device__ __forceinline__ float gelu_f(float x) {
    return 0.5f * x * (1.0f + erff(x * 0.70710678118654752440f));
}
__device__ __forceinline__ uint32_t sm_u32(const void* p) {
    uint32_t a;
    asm("{ .reg .u64 t; cvta.to.shared.u64 t, %1; cvt.u32.u64 %0, t; }" : "=r"(a) : "l"(p));
    return a;
}
__device__ __forceinline__ void split1(float v, bf16& h, bf16& l) {
    h = __float2bfloat16_rn(v);
    l = __float2bfloat16_rn(v - __bfloat162float(h));
}

// ---------------- mma.sync / ldmatrix wrappers ----------------
__device__ __forceinline__ void ldm_x4(uint32_t* r, uint32_t addr) {
    asm volatile("ldmatrix.sync.aligned.m8n8.x4.shared.b16 {%0,%1,%2,%3}, [%4];"
        : "=r"(r[0]), "=r"(r[1]), "=r"(r[2]), "=r"(r[3]) : "r"(addr));
}
__device__ __forceinline__ void mma_bf(float* d, const uint32_t* a, const uint32_t* b) {
    asm volatile("mma.sync.aligned.m16n8k16.row.col.f32.bf16.bf16.f32 "
        "{%0,%1,%2,%3}, {%4,%5,%6,%7}, {%8,%9}, {%0,%1,%2,%3};"
        : "+f"(d[0]), "+f"(d[1]), "+f"(d[2]), "+f"(d[3])
        : "r"(a[0]), "r"(a[1]), "r"(a[2]), "r"(a[3]), "r"(b[0]), "r"(b[1]));
}
__device__ __forceinline__ void cpa16(uint32_t dst, const void* src) {
    asm volatile("cp.async.ca.shared.global [%0], [%1], 16;" :: "r"(dst), "l"(src) : "memory");
}
#define CP_COMMIT() asm volatile("cp.async.commit_group;" ::: "memory")
#define CP_WAIT0()  asm volatile("cp.async.wait_group 0;" ::: "memory")

// ---------------- bf16 hi/lo tensor-core GEMM ----------------
// C[M,NOUT] = A[M,512] @ W[NOUT,512]^T (+bias, +res / gelu)
// A,W given as pre-split bf16 hi/lo. 3 passes: Ah*Wh + Ah*Wl + Al*Wh, fp32 accum.
// BM=BN=128, BK=32, 512 threads (16 warps, 4m x 4n grid, warp tile 32x32).
#define TILE_B 10240u              // 128 rows * 80B (32 bf16 + 16B pad)
#define BUF_B  (4u*TILE_B)         // Ah, Al, Wh, Wl
#define SMEM_G (2u*BUF_B)          // 81920 double buffered

// EPI: 0 = +bias -> fp32 C ; 1 = +bias+res -> fp32 C ; 2 = +bias,gelu -> bf16 hi/lo Ch/Cl
template<int EPI, int NOUT>
__global__ __launch_bounds__(512)
void mma_gemm(const bf16* __restrict__ Ah_g, const bf16* __restrict__ Al_g,
              const bf16* __restrict__ Wh_g, const bf16* __restrict__ Wl_g,
              const float* __restrict__ bias, const float* __restrict__ res,
              float* __restrict__ C, bf16* __restrict__ Ch, bf16* __restrict__ Cl)
{
    extern __shared__ char smraw[];
    const uint32_t sb = sm_u32(smraw);

    const int tid  = threadIdx.x;
    const int lane = tid & 31;
    const int wid  = tid >> 5;
    const int wm   = wid >> 2;        // 0..3
    const int wn   = wid & 3;         // 0..3
    const int bm   = blockIdx.y * 128;
    const int bn   = blockIdx.x * 128;

    // loader mapping: each thread owns one 16B chunk per tile
    const int lrow = tid >> 2;        // 0..127
    const int lq   = tid & 3;         // 0..3
    const uint32_t sdst = (uint32_t)(lrow * 80 + lq * 16);
    const bf16* apH = Ah_g + (size_t)(bm + lrow) * 512 + lq * 8;
    const bf16* apL = Al_g + (size_t)(bm + lrow) * 512 + lq * 8;
    const bf16* wpH = Wh_g + (size_t)(bn + lrow) * 512 + lq * 8;
    const bf16* wpL = Wl_g + (size_t)(bn + lrow) * 512 + lq * 8;

    float acc[2][4][4];
#pragma unroll
    for (int mi = 0; mi < 2; mi++)
#pragma unroll
        for (int ni = 0; ni < 4; ni++)
#pragma unroll
            for (int r = 0; r < 4; r++) acc[mi][ni][r] = 0.f;

    // prologue: load k-tile 0 into buffer 0
    {
        uint32_t b0 = sb;
        cpa16(b0 + sdst,            apH);
        cpa16(b0 + TILE_B + sdst,   apL);
        cpa16(b0 + 2*TILE_B + sdst, wpH);
        cpa16(b0 + 3*TILE_B + sdst, wpL);
        CP_COMMIT();
        CP_WAIT0();
        __syncthreads();
    }

    // ldmatrix base offsets for this warp/lane
    const uint32_t a_off = (uint32_t)((wm * 32 + (lane & 15)) * 80 + ((lane >> 4) << 4));
    const uint32_t b_off = (uint32_t)((wn * 32 + ((lane >> 4) << 3) + (lane & 7)) * 80
                                      + (((lane >> 3) & 1) << 4));

#pragma unroll 1
    for (int kt = 0; kt < 16; kt++) {
        const uint32_t cur = sb + (uint32_t)(kt & 1) * BUF_B;
        if (kt < 15) {
            const uint32_t nxt = sb + (uint32_t)((kt + 1) & 1) * BUF_B;
            const int ko = (kt + 1) * 32;
            cpa16(nxt + sdst,            apH + ko);
            cpa16(nxt + TILE_B + sdst,   apL + ko);
            cpa16(nxt + 2*TILE_B + sdst, wpH + ko);
            cpa16(nxt + 3*TILE_B + sdst, wpL + ko);
            CP_COMMIT();
        }

        const uint32_t Ah = cur, Al = cur + TILE_B, Bh = cur + 2*TILE_B, Bl = cur + 3*TILE_B;
#pragma unroll
        for (int kk = 0; kk < 2; kk++) {
            const uint32_t kb = kk * 32;
            uint32_t ah[2][4], al[2][4], bh[2][4], bl[2][4];
            ldm_x4(ah[0], Ah + a_off + kb);
            ldm_x4(ah[1], Ah + a_off + 16*80 + kb);
            ldm_x4(bh[0], Bh + b_off + kb);
            ldm_x4(bh[1], Bh + b_off + 16*80 + kb);
#pragma unroll
            for (int mi = 0; mi < 2; mi++)
#pragma unroll
                for (int ni = 0; ni < 4; ni++)
                    mma_bf(acc[mi][ni], ah[mi], &bh[ni >> 1][(ni & 1) * 2]);
            ldm_x4(bl[0], Bl + b_off + kb);
            ldm_x4(bl[1], Bl + b_off + 16*80 + kb);
#pragma unroll
            for (int mi = 0; mi < 2; mi++)
#pragma unroll
                for (int ni = 0; ni < 4; ni++)
                    mma_bf(acc[mi][ni], ah[mi], &bl[ni >> 1][(ni & 1) * 2]);
            ldm_x4(al[0], Al + a_off + kb);
            ldm_x4(al[1], Al + a_off + 16*80 + kb);
#pragma unroll
            for (int mi = 0; mi < 2; mi++)
#pragma unroll
                for (int ni = 0; ni < 4; ni++)
                    mma_bf(acc[mi][ni], al[mi], &bh[ni >> 1][(ni & 1) * 2]);
        }

        if (kt < 15) {
            CP_WAIT0();
            __syncthreads();
        }
    }

    // ---- epilogue ----
    const int r0 = bm + wm * 32 + (lane >> 2);
    const int c0 = bn + wn * 32 + (lane & 3) * 2;
#pragma unroll
    for (int mi = 0; mi < 2; mi++) {
#pragma unroll
        for (int ni = 0; ni < 4; ni++) {
            const int col = c0 + ni * 8;
            float2 bv = *(const float2*)&bias[col];
#pragma unroll
            for (int h = 0; h < 2; h++) {
                const int row = r0 + mi * 16 + h * 8;
                float v0 = acc[mi][ni][h * 2 + 0] + bv.x;
                float v1 = acc[mi][ni][h * 2 + 1] + bv.y;
                if (EPI == 1) {
                    float2 rr = *(const float2*)&res[(size_t)row * 512 + col];
                    v0 += rr.x; v1 += rr.y;
                }
                if (EPI == 2) {
                    v0 = gelu_f(v0); v1 = gelu_f(v1);
                    bf16 h0, l0, h1, l1;
                    split1(v0, h0, l0); split1(v1, h1, l1);
                    __nv_bfloat162 hp; hp.x = h0; hp.y = h1;
                    __nv_bfloat162 lp; lp.x = l0; lp.y = l1;
                    *(__nv_bfloat162*)&Ch[(size_t)row * NOUT + col] = hp;
                    *(__nv_bfloat162*)&Cl[(size_t)row * NOUT + col] = lp;
                } else {
                    *(float2*)&C[(size_t)row * NOUT + col] = make_float2(v0, v1);
                }
            }
        }
    }
}

// ---------------- weight splitter ----------------
__global__ void splitw_kernel(const float* __restrict__ src, bf16* __restrict__ hi,
                              bf16* __restrict__ lo, int n4) {
    int i = blockIdx.x * 256 + threadIdx.x;
    if (i >= n4) return;
    float4 v = *(const float4*)(src + i * 4);
    bf16 h0,l0,h1,l1,h2,l2,h3,l3;
    split1(v.x, h0, l0); split1(v.y, h1, l1);
    split1(v.z, h2, l2); split1(v.w, h3, l3);
    __nv_bfloat162 hp0; hp0.x=h0; hp0.y=h1;
    __nv_bfloat162 hp1; hp1.x=h2; hp1.y=h3;
    __nv_bfloat162 lp0; lp0.x=l0; lp0.y=l1;
    __nv_bfloat162 lp1; lp1.x=l2; lp1.y=l3;
    *(__nv_bfloat162*)&hi[i*4]   = hp0;
    *(__nv_bfloat162*)&hi[i*4+2] = hp1;
    *(__nv_bfloat162*)&lo[i*4]   = lp0;
    *(__nv_bfloat162*)&lo[i*4+2] = lp1;
}

// ---------------- kernel 1: boxes -> rel features ----------------
__global__ void rel_kernel(const float* __restrict__ boxes, float* __restrict__ rel) {
    int gw   = (blockIdx.x * blockDim.x + threadIdx.x) >> 5;
    int lane = threadIdx.x & 31;
    if (gw >= B_) return;

    float cx = 0.f, cy = 0.f, bw = 0.f, bh = 0.f;
    if (lane < N_) {
        float4 bx = *(const float4*)(boxes + ((size_t)gw * N_ + lane) * 4);
        cx = (bx.x + bx.z) * 0.5f * (1.0f / 512.0f);
        cy = (bx.y + bx.w) * 0.5f * (1.0f / 512.0f);
        bw = fabsf(bx.z - bx.x) * (1.0f / 512.0f);
        bh = fabsf(bx.w - bx.y) * (1.0f / 512.0f);
    }
    float bd[5] = {INFINITY, INFINITY, INFINITY, INFINITY, INFINITY};
    int   bj[5] = {0, 0, 0, 0, 0};
#pragma unroll
    for (int j = 0; j < N_; j++) {
        float cxj = __shfl_sync(0xffffffffu, cx, j);
        float cyj = __shfl_sync(0xffffffffu, cy, j);
        float dx = cx - cxj, dy = cy - cyj;
        float d  = dx * dx + dy * dy;
        if (lane < N_ && j != lane && d < bd[4]) {
            int p = 4;
            while (p > 0 && d < bd[p-1]) { bd[p] = bd[p-1]; bj[p] = bj[p-1]; p--; }
            bd[p] = d; bj[p] = j;
        }
    }
#pragma unroll
    for (int k = 0; k < 5; k++) {
        int j = bj[k];
        float cxj = __shfl_sync(0xffffffffu, cx, j);
        float cyj = __shfl_sync(0xffffffffu, cy, j);
        float bwj = __shfl_sync(0xffffffffu, bw, j);
        float bhj = __shfl_sync(0xffffffffu, bh, j);
        if (lane < N_) {
            float4 o4 = make_float4(cxj - cx, cyj - cy, bwj - bw, bhj - bh);
            *(float4*)(rel + ((size_t)gw * N_ + lane) * 20 + k * 4) = o4;
        }
    }
}

// ---------------- kernel 2: x = rel @ w_in^T + b_in (also writes bf16 hi/lo) ----------------
__global__ void inproj_kernel(const float* __restrict__ rel, const float* __restrict__ w_in,
                              const float* __restrict__ b_in, float* __restrict__ x,
                              bf16* __restrict__ xh, bf16* __restrict__ xl) {
    __shared__ float ws[20 * 512];
    __shared__ float rs[32 * 20];
    int tid = threadIdx.x;
    int t0  = blockIdx.x * 32;

    for (int i = tid; i < 20 * 512; i += 256) {
        int d = i / 20, j = i % 20;
        ws[j * 512 + d] = w_in[i];
    }
    for (int i = tid; i < 32 * 20; i += 256)
        rs[i] = rel[(size_t)t0 * 20 + i];
    __syncthreads();

    for (int i = tid; i < 32 * 512; i += 256) {
        int tt = i >> 9, d = i & 511;
        float s = b_in[d];
#pragma unroll
        for (int j = 0; j < 20; j++)
            s = fmaf(rs[tt * 20 + j], ws[j * 512 + d], s);
        size_t idx = (size_t)(t0 + tt) * 512 + d;
        x[idx] = s;
        bf16 h, l; split1(s, h, l);
        xh[idx] = h; xl[idx] = l;
    }
}

// ---------------- attention kernel: one block per batch (writes bf16 hi/lo) ----------------
__global__ void attn_kernel(const float* __restrict__ qkv,
                            bf16* __restrict__ oh, bf16* __restrict__ ol) {
    extern __shared__ __align__(16) float s[];   // 10 * 1540 floats
    __shared__ float satt[200];
    const int b   = blockIdx.x;
    const int tid = threadIdx.x;
    const float* src = qkv + (size_t)b * (N_ * 3 * D_);

    for (int i = tid; i < (N_ * 3 * D_) / 4; i += 256) {
        int e = i * 4;
        int r = e / 1536, c = e % 1536;
        float4 v = *(const float4*)(src + e);
        *(float4*)(s + r * 1540 + c) = v;
    }
    __syncthreads();

    if (tid < 200) {
        int h = tid / 100;
        int i = (tid / 10) % 10;
        int j = tid % 10;
        const float* qp = s + i * 1540 + h * 256;
        const float* kp = s + j * 1540 + 512 + h * 256;
        float acc = 0.f;
#pragma unroll 8
        for (int d = 0; d < 256; d++) acc = fmaf(qp[d], kp[d], acc);
        satt[tid] = acc * 0.0625f;
    }
    __syncthreads();

    if (tid < 20) {
        int base = tid * 10;
        float m = satt[base];
#pragma unroll
        for (int j = 1; j < 10; j++) m = fmaxf(m, satt[base + j]);
        float e[10]; float sum = 0.f;
#pragma unroll
        for (int j = 0; j < 10; j++) { e[j] = expf(satt[base + j] - m); sum += e[j]; }
        float inv = 1.0f / sum;
#pragma unroll
        for (int j = 0; j < 10; j++) satt[base + j] = e[j] * inv;
    }
    __syncthreads();

    bf16* dsth = oh + (size_t)b * (N_ * D_);
    bf16* dstl = ol + (size_t)b * (N_ * D_);
    for (int idx = tid; idx < N_ * D_; idx += 256) {
        int d  = idx & 255;
        int hi = idx >> 8;
        int i  = hi % 10, h = hi / 10;
        const float* ap = satt + h * 100 + i * 10;
        const float* vp = s + 1024 + h * 256 + d;
        float acc = 0.f;
#pragma unroll
        for (int j = 0; j < 10; j++) acc = fmaf(ap[j], vp[j * 1540], acc);
        bf16 hh, ll; split1(acc, hh, ll);
        dsth[i * 512 + h * 256 + d] = hh;
        dstl[i * 512 + h * 256 + d] = ll;
    }
}

// ---------------- layernorm (fp32 out + bf16 hi/lo out) ----------------
__global__ void ln_kernel(const float* __restrict__ y, const float* __restrict__ g,
                          const float* __restrict__ bt, float* __restrict__ out,
                          bf16* __restrict__ outh, bf16* __restrict__ outl) {
    int row  = blockIdx.x * 8 + (threadIdx.x >> 5);
    int lane = threadIdx.x & 31;
    const float* p = y + (size_t)row * 512;
    float v[16];
#pragma unroll
    for (int q = 0; q < 4; q++) {
        float4 t = *(const float4*)(p + q * 128 + lane * 4);
        v[q*4+0] = t.x; v[q*4+1] = t.y; v[q*4+2] = t.z; v[q*4+3] = t.w;
    }
    float s = 0.f;
#pragma unroll
    for (int k = 0; k < 16; k++) s += v[k];
    s = warp_sum(s);
    float mu = s * (1.0f / 512.0f);
    float qs = 0.f;
#pragma unroll
    for (int k = 0; k < 16; k++) { float d = v[k] - mu; qs += d * d; }
    qs = warp_sum(qs);
    float inv = rsqrtf(qs * (1.0f / 512.0f) + 1e-5f);

    float* op = out + (size_t)row * 512;
#pragma unroll
    for (int q = 0; q < 4; q++) {
        int d0 = q * 128 + lane * 4;
        float r[4];
#pragma unroll
        for (int e = 0; e < 4; e++)
            r[e] = (v[q*4+e] - mu) * inv * g[d0+e] + bt[d0+e];
        *(float4*)(op + d0) = make_float4(r[0], r[1], r[2], r[3]);
        bf16 h0,l0,h1,l1,h2,l2,h3,l3;
        split1(r[0],h0,l0); split1(r[1],h1,l1); split1(r[2],h2,l2); split1(r[3],h3,l3);
        __nv_bfloat162 hp0; hp0.x=h0; hp0.y=h1;
        __nv_bfloat162 hp1; hp1.x=h2; hp1.y=h3;
        __nv_bfloat162 lp0; lp0.x=l0; lp0.y=l1;
        __nv_bfloat162 lp1; lp1.x=l2; lp1.y=l3;
        *(__nv_bfloat162*)&outh[(size_t)row*512 + d0]   = hp0;
        *(__nv_bfloat162*)&outh[(size_t)row*512 + d0+2] = hp1;
        *(__nv_bfloat162*)&outl[(size_t)row*512 + d0]   = lp0;
        *(__nv_bfloat162*)&outl[(size_t)row*512 + d0+2] = lp1;
    }
}

// ---------------- fused LN2 + LNf ----------------
__global__ void ln2f_kernel(const float* __restrict__ y,
                            const float* __restrict__ g2, const float* __restrict__ b2,
                            const float* __restrict__ gf, const float* __restrict__ bf_,
                            float* __restrict__ out) {
    int row  = blockIdx.x * 8 + (threadIdx.x >> 5);
    int lane = threadIdx.x & 31;
    const float* p = y + (size_t)row * 512;
    float v[16];
#pragma unroll
    for (int q = 0; q < 4; q++) {
        float4 t = *(const float4*)(p + q * 128 + lane * 4);
        v[q*4+0] = t.x; v[q*4+1] = t.y; v[q*4+2] = t.z; v[q*4+3] = t.w;
    }
    float s = 0.f;
#pragma unroll
    for (int k = 0; k < 16; k++) s += v[k];
    s = warp_sum(s);
    float mu = s * (1.0f / 512.0f);
    float qs = 0.f;
#pragma unroll
    for (int k = 0; k < 16; k++) { float d = v[k] - mu; qs += d * d; }
    qs = warp_sum(qs);
    float inv = rsqrtf(qs * (1.0f / 512.0f) + 1e-5f);
#pragma unroll
    for (int k = 0; k < 16; k++) {
        int d = (k >> 2) * 128 + lane * 4 + (k & 3);
        v[k] = (v[k] - mu) * inv * g2[d] + b2[d];
    }
    s = 0.f;
#pragma unroll
    for (int k = 0; k < 16; k++) s += v[k];
    s = warp_sum(s);
    float mu2 = s * (1.0f / 512.0f);
    qs = 0.f;
#pragma unroll
    for (int k = 0; k < 16; k++) { float d = v[k] - mu2; qs += d * d; }
    qs = warp_sum(qs);
    float inv2 = rsqrtf(qs * (1.0f / 512.0f) + 1e-5f);

    float* op = out + (size_t)row * 512;
#pragma unroll
    for (int q = 0; q < 4; q++) {
        int d0 = q * 128 + lane * 4;
        float4 r;
        r.x = (v[q*4+0] - mu2) * inv2 * gf[d0+0] + bf_[d0+0];
        r.y = (v[q*4+1] - mu2) * inv2 * gf[d0+1] + bf_[d0+1];
        r.z = (v[q*4+2] - mu2) * inv2 * gf[d0+2] + bf_[d0+2];
        r.w = (v[q*4+3] - mu2) * inv2 * gf[d0+3] + bf_[d0+3];
        *(float4*)(op + d0) = r;
    }
}

// ---------------- launcher ----------------
extern "C" void kernel_launch(void* const* d_in, const int* in_sizes, int n_in,
                              void* d_out, int out_size) {
    const float* boxes = (const float*)d_in[0];
    const float* w_in  = (const float*)d_in[1];
    const float* b_in  = (const float*)d_in[2];
    const float* wqkv  = (const float*)d_in[3];
    const float* bqkv  = (const float*)d_in[4];
    const float* wo    = (const float*)d_in[5];
    const float* bo    = (const float*)d_in[6];
    const float* ln1w  = (const float*)d_in[7];
    const float* ln1b  = (const float*)d_in[8];
    const float* w1    = (const float*)d_in[9];
    const float* b1    = (const float*)d_in[10];
    const float* w2    = (const float*)d_in[11];
    const float* b2    = (const float*)d_in[12];
    const float* ln2w  = (const float*)d_in[13];
    const float* ln2b  = (const float*)d_in[14];
    const float* lnfw  = (const float*)d_in[15];
    const float* lnfb  = (const float*)d_in[16];
    float* out = (float*)d_out;

    float *rel, *x, *x1, *yb, *qkv;
    bf16 *xh, *xl, *ath, *atl, *x1h, *x1l, *hh, *hl;
    bf16 *wqh, *wql, *woh, *wol, *w1h, *w1l, *w2h, *w2l;
    cudaGetSymbolAddress((void**)&rel, g_rel);
    cudaGetSymbolAddress((void**)&x,   g_x);
    cudaGetSymbolAddress((void**)&x1,  g_x1);
    cudaGetSymbolAddress((void**)&yb,  g_y);
    cudaGetSymbolAddress((void**)&qkv, g_qkv);
    cudaGetSymbolAddress((void**)&xh,  g_xh);
    cudaGetSymbolAddress((void**)&xl,  g_xl);
    cudaGetSymbolAddress((void**)&ath, g_ath);
    cudaGetSymbolAddress((void**)&atl, g_atl);
    cudaGetSymbolAddress((void**)&x1h, g_x1h);
    cudaGetSymbolAddress((void**)&x1l, g_x1l);
    cudaGetSymbolAddress((void**)&hh,  g_hh);
    cudaGetSymbolAddress((void**)&hl,  g_hl);
    cudaGetSymbolAddress((void**)&wqh, g_wqh);
    cudaGetSymbolAddress((void**)&wql, g_wql);
    cudaGetSymbolAddress((void**)&woh, g_woh);
    cudaGetSymbolAddress((void**)&wol, g_wol);
    cudaGetSymbolAddress((void**)&w1h, g_w1h);
    cudaGetSymbolAddress((void**)&w1l, g_w1l);
    cudaGetSymbolAddress((void**)&w2h, g_w2h);
    cudaGetSymbolAddress((void**)&w2l, g_w2l);

    cudaFuncSetAttribute(mma_gemm<0,1536>, cudaFuncAttributeMaxDynamicSharedMemorySize, SMEM_G);
    cudaFuncSetAttribute(mma_gemm<1,512>,  cudaFuncAttributeMaxDynamicSharedMemorySize, SMEM_G);
    cudaFuncSetAttribute(mma_gemm<2,512>,  cudaFuncAttributeMaxDynamicSharedMemorySize, SMEM_G);

    // 0) split weights
    splitw_kernel<<<(3*D_*D_/4 + 255)/256, 256>>>(wqkv, wqh, wql, 3*D_*D_/4);
    splitw_kernel<<<(D_*D_/4 + 255)/256, 256>>>(wo, woh, wol, D_*D_/4);
    splitw_kernel<<<(D_*D_/4 + 255)/256, 256>>>(w1, w1h, w1l, D_*D_/4);
    splitw_kernel<<<(D_*D_/4 + 255)/256, 256>>>(w2, w2h, w2l, D_*D_/4);
    // 1) relationships
    rel_kernel<<<B_/4, 128>>>(boxes, rel);
    // 2) input projection (+split)
    inproj_kernel<<<T_/32, 256>>>(rel, w_in, b_in, x, xh, xl);
    // 3) qkv = x @ wqkv^T + bqkv
    mma_gemm<0,1536><<<dim3(12, T_/128), 512, SMEM_G>>>(xh, xl, wqh, wql, bqkv, nullptr, qkv, nullptr, nullptr);
    // 4) attention (+split)
    int attn_smem = 10 * 1540 * (int)sizeof(float);
    cudaFuncSetAttribute(attn_kernel, cudaFuncAttributeMaxDynamicSharedMemorySize, attn_smem);
    attn_kernel<<<B_, 256, attn_smem>>>(qkv, ath, atl);
    // 5) y1 = x + att @ wo^T + bo
    mma_gemm<1,512><<<dim3(4, T_/128), 512, SMEM_G>>>(ath, atl, woh, wol, bo, x, yb, nullptr, nullptr);
    // 6) x1 = LN1(y1) (+split)
    ln_kernel<<<T_/8, 256>>>(yb, ln1w, ln1b, x1, x1h, x1l);
    // 7) h = gelu(x1 @ w1^T + b1)  -> bf16 hi/lo
    mma_gemm<2,512><<<dim3(4, T_/128), 512, SMEM_G>>>(x1h, x1l, w1h, w1l, b1, nullptr, nullptr, hh, hl);
    // 8) y2 = x1 + h @ w2^T + b2
    mma_gemm<1,512><<<dim3(4, T_/128), 512, SMEM_G>>>(hh, hl, w2h, w2l, b2, x1, yb, nullptr, nullptr);
    // 9) out = LNf(LN2(y2))
    ln2f_kernel<<<T_/8, 256>>>(yb, ln2w, ln2b, lnfw, lnfb, out);
}